// round 1
// baseline (speedup 1.0000x reference)
#include <cuda_runtime.h>
#include <math.h>

#define RESX   128
#define NVOX   (RESX*RESX*RESX)
#define NRAYS  1024
#define NS     891
#define NTH    128

#define ACT_SHIFT (-4.5951198501345898f)   // log(1/(1-0.01)-1)

// normals grid scratch: 3 x 128^3 floats (~25 MB), static device global (allowed)
__device__ float g_norm[3*NVOX];

// ---------------------------------------------------------------------------
// Kernel 1: 5x5x5 cross-correlation of density (grid channel 0) with sobel
// kernel (3,1,5,5,5), zero padding 2, then per-voxel: n = -conv / max(|conv|,1e-12)
// Tiled: block (32 c, 8 b), each thread computes 4 outputs along a (slow dim).
// ---------------------------------------------------------------------------
__global__ void __launch_bounds__(256) conv_kernel(const float* __restrict__ dens,
                                                   const float* __restrict__ kern)
{
    __shared__ float sk[375];
    __shared__ float tile[8*12*36];

    int tc = threadIdx.x;          // 0..31 (c, fastest dim)
    int tb = threadIdx.y;          // 0..7  (b)
    int tid = tb*32 + tc;
    int c0 = blockIdx.x*32;
    int b0 = blockIdx.y*8;
    int a0 = blockIdx.z*4;

    for (int i=tid; i<375; i+=256) sk[i] = kern[i];
    for (int i=tid; i<8*12*36; i+=256){
        int ic = i % 36; int r = i / 36; int ib = r % 12; int ia = r / 12;
        int ga = a0 - 2 + ia, gb = b0 - 2 + ib, gc = c0 - 2 + ic;
        float v = 0.f;
        if ((unsigned)ga < 128u && (unsigned)gb < 128u && (unsigned)gc < 128u)
            v = dens[(ga*128 + gb)*128 + gc];
        tile[i] = v;
    }
    __syncthreads();

    float s0[4] = {0,0,0,0}, s1[4] = {0,0,0,0}, s2[4] = {0,0,0,0};
    for (int db=0; db<5; db++){
        for (int dc=0; dc<5; dc++){
            float tv[8];
            #pragma unroll
            for (int ia=0; ia<8; ia++)
                tv[ia] = tile[(ia*12 + tb + db)*36 + tc + dc];
            #pragma unroll
            for (int da=0; da<5; da++){
                float k0 = sk[0*125 + da*25 + db*5 + dc];
                float k1 = sk[1*125 + da*25 + db*5 + dc];
                float k2 = sk[2*125 + da*25 + db*5 + dc];
                #pragma unroll
                for (int v=0; v<4; v++){
                    float x = tv[v+da];
                    s0[v] = fmaf(k0, x, s0[v]);
                    s1[v] = fmaf(k1, x, s1[v]);
                    s2[v] = fmaf(k2, x, s2[v]);
                }
            }
        }
    }
    #pragma unroll
    for (int v=0; v<4; v++){
        int idx = ((a0+v)*128 + (b0+tb))*128 + (c0+tc);
        float n0 = s0[v], n1 = s1[v], n2 = s2[v];
        float len = sqrtf(n0*n0 + n1*n1 + n2*n2);
        float inv = -1.f / fmaxf(len, 1e-12f);
        g_norm[idx]          = n0*inv;
        g_norm[NVOX + idx]   = n1*inv;
        g_norm[2*NVOX + idx] = n2*inv;
    }
}

// ---------------------------------------------------------------------------
// packed fp32x2 helpers (bit-exact fp32 math, 2x FFMA throughput on sm_103a)
// ---------------------------------------------------------------------------
typedef unsigned long long u64;
__device__ __forceinline__ u64 f2pack(float lo, float hi){
    u64 r; asm("mov.b64 %0,{%1,%2};" : "=l"(r) : "f"(lo), "f"(hi)); return r;
}
__device__ __forceinline__ void f2unpack(u64 v, float& lo, float& hi){
    asm("mov.b64 {%0,%1},%2;" : "=f"(lo), "=f"(hi) : "l"(v));
}
__device__ __forceinline__ u64 ffma2(u64 a, u64 b, u64 c){
    u64 d; asm("fma.rn.f32x2 %0,%1,%2,%3;" : "=l"(d) : "l"(a), "l"(b), "l"(c)); return d;
}
// h[32] (64 neurons packed) += v * row[0..63]
__device__ __forceinline__ void accum_row(u64* h, float v, const float* row){
    u64 vv = f2pack(v, v);
    const u64* wr = (const u64*)row;
    #pragma unroll
    for (int k=0; k<32; k++) h[k] = ffma2(vv, wr[k], h[k]);
}

// trilinear setup: a<-pt.x (slow), b<-pt.y, c<-pt.z (fast); idx=(a*128+b)*128+c
__device__ __forceinline__ void tri_setup(float px, float py, float pz,
                                          int* off, float* w)
{
    float ga = (px + 1.f)*0.5f*127.f;
    float gb = (py + 1.f)*0.5f*127.f;
    float gc = (pz + 1.f)*0.5f*127.f;
    float fa0 = floorf(ga), fb0 = floorf(gb), fc0 = floorf(gc);
    float fa = ga - fa0, fb = gb - fb0, fc = gc - fc0;
    int a0 = min(max((int)fa0, 0), 127);
    int b0 = min(max((int)fb0, 0), 127);
    int c0 = min(max((int)fc0, 0), 127);
    int a1 = min(a0+1, 127), b1 = min(b0+1, 127), c1 = min(c0+1, 127);
    int A0 = a0*16384, A1 = a1*16384, B0 = b0*128, B1 = b1*128;
    off[0]=A0+B0+c0; off[1]=A0+B0+c1; off[2]=A0+B1+c0; off[3]=A0+B1+c1;
    off[4]=A1+B0+c0; off[5]=A1+B0+c1; off[6]=A1+B1+c0; off[7]=A1+B1+c1;
    float wa0 = 1.f-fa, wb0 = 1.f-fb, wc0 = 1.f-fc;
    w[0]=wa0*wb0*wc0; w[1]=wa0*wb0*fc; w[2]=wa0*fb*wc0; w[3]=wa0*fb*fc;
    w[4]=fa*wb0*wc0;  w[5]=fa*wb0*fc;  w[6]=fa*fb*wc0;  w[7]=fa*fb*fc;
}

// shared layout (float offsets)
#define OFF_W0  0
#define OFF_B0  3456
#define OFF_W1  3520
#define OFF_B1  7616
#define OFF_W2  7680
#define OFF_B2  11776
#define OFF_W3  11840
#define OFF_B3  12032
#define OFF_AW  12036
#define OFF_HST 12928
#define OFF_RED 21248
#define SH_FLOATS 21264
#define SMEM_BYTES (SH_FLOATS*4)

// ---------------------------------------------------------------------------
// Kernel 2: one block per ray. Phase A: alpha per sample. Phase B: sequential
// transmittance scan (thread 0). Phase C: gathers + reflect-embed + MLP (f32x2).
// ---------------------------------------------------------------------------
__global__ void __launch_bounds__(NTH) march_kernel(
    const float* __restrict__ ro,  const float* __restrict__ rdv,
    const float* __restrict__ vdv, const float* __restrict__ grid,
    const float* __restrict__ w0,  const float* __restrict__ b0,
    const float* __restrict__ w1,  const float* __restrict__ b1,
    const float* __restrict__ w2,  const float* __restrict__ b2,
    const float* __restrict__ w3,  const float* __restrict__ b3,
    float* __restrict__ out)
{
    extern __shared__ float sh[];
    int tid = threadIdx.x;
    int rid = blockIdx.x;

    // cooperative weight load into shared
    for (int i=tid; i<3456; i+=NTH) sh[OFF_W0+i] = w0[i];
    for (int i=tid; i<64;   i+=NTH) sh[OFF_B0+i] = b0[i];
    for (int i=tid; i<4096; i+=NTH) sh[OFF_W1+i] = w1[i];
    for (int i=tid; i<64;   i+=NTH) sh[OFF_B1+i] = b1[i];
    for (int i=tid; i<4096; i+=NTH) sh[OFF_W2+i] = w2[i];
    for (int i=tid; i<64;   i+=NTH) sh[OFF_B2+i] = b2[i];
    for (int i=tid; i<192;  i+=NTH) sh[OFF_W3+i] = w3[i];
    if (tid < 3) sh[OFF_B3+tid] = b3[tid];

    float ox = ro[rid*3+0], oy = ro[rid*3+1], oz = ro[rid*3+2];
    float dx = rdv[rid*3+0], dy = rdv[rid*3+1], dz = rdv[rid*3+2];
    float vx = vdv[rid*3+0], vy = vdv[rid*3+1], vz = vdv[rid*3+2];

    float vecx = (dx == 0.f) ? 1e-6f : dx;
    float vecy = (dy == 0.f) ? 1e-6f : dy;
    float vecz = (dz == 0.f) ? 1e-6f : dz;
    float rax = ( 1.f - ox)/vecx, rbx = (-1.f - ox)/vecx;
    float ray_ = ( 1.f - oy)/vecy, rby = (-1.f - oy)/vecy;
    float raz = ( 1.f - oz)/vecz, rbz = (-1.f - oz)/vecz;
    float tmin = fmaxf(fmaxf(fminf(rax,rbx), fminf(ray_,rby)), fminf(raz,rbz));
    tmin = fminf(fmaxf(tmin, 0.2f), 3.0f);
    float tmax = fminf(fminf(fmaxf(rax,rbx), fmaxf(ray_,rby)), fmaxf(raz,rbz));
    tmax = fminf(fmaxf(tmax, 0.2f), 3.0f);
    bool maskray = (tmax <= tmin);
    float invn = 1.f / sqrtf(dx*dx + dy*dy + dz*dz);

    // ---------------- Phase A: alpha per sample ----------------
    for (int s=tid; s<NS; s+=NTH){
        float t  = tmin + (0.0078125f * (float)s) * invn;
        float px = fmaf(dx, t, ox), py = fmaf(dy, t, oy), pz = fmaf(dz, t, oz);
        bool in = (!maskray) &&
                  !(px < -1.f || px > 1.f || py < -1.f || py > 1.f || pz < -1.f || pz > 1.f);
        float a = 0.f;
        if (in){
            int off[8]; float wc[8];
            tri_setup(px, py, pz, off, wc);
            float l0 = 0.f;
            #pragma unroll
            for (int k=0; k<8; k++) l0 = fmaf(wc[k], __ldg(grid + off[k]), l0);
            float xs = l0 + ACT_SHIFT;
            float sp = fmaxf(xs, 0.f) + log1pf(expf(-fabsf(xs)));
            a = 1.f - expf(-sp*0.5f);
        }
        sh[OFF_AW + s] = a;
    }
    __syncthreads();

    // ---------------- Phase B: transmittance scan (matches cumprod order) ---
    if (tid == 0){
        float T = 1.f;
        for (int s=0; s<NS; s++){
            float a = sh[OFF_AW + s];
            sh[OFF_AW + s] = a * T;          // weight = alpha * T_exclusive
            T *= fmaxf(1.f - a, 1e-10f);
        }
        sh[OFF_RED + 15] = T;                // final transmittance (BG term)
    }
    __syncthreads();

    // ---------------- Phase C: gathers + MLP ----------------
    float acc0 = 0.f, acc1 = 0.f, acc2 = 0.f;
    float* hst = sh + OFF_HST + tid*65;      // conflict-free per-thread stage

    for (int s=tid; s<NS; s+=NTH){
        float t  = tmin + (0.0078125f * (float)s) * invn;
        float px = fmaf(dx, t, ox), py = fmaf(dy, t, oy), pz = fmaf(dz, t, oz);
        bool in = (!maskray) &&
                  !(px < -1.f || px > 1.f || py < -1.f || py > 1.f || pz < -1.f || pz > 1.f);
        if (!in) continue;

        float wgt = sh[OFF_AW + s];
        int off[8]; float wc[8];
        tri_setup(px, py, pz, off, wc);

        // layer 0 accumulators (64 neurons packed into 32 x f32x2)
        u64 h[32];
        {
            const u64* bp = (const u64*)(sh + OFF_B0);
            #pragma unroll
            for (int k=0; k<32; k++) h[k] = bp[k];
        }

        // rgb latent channels 1..15, streamed into layer0 with prefetch
        float cv[8];
        #pragma unroll
        for (int k=0; k<8; k++) cv[k] = __ldg(grid + NVOX + off[k]);
        for (int ch=1; ch<=15; ++ch){
            float nv[8];
            if (ch < 15){
                const float* gp = grid + (ch+1)*NVOX;
                #pragma unroll
                for (int k=0; k<8; k++) nv[k] = __ldg(gp + off[k]);
            }
            float v = 0.f;
            #pragma unroll
            for (int k=0; k<8; k++) v = fmaf(wc[k], cv[k], v);
            accum_row(h, v, sh + OFF_W0 + (ch-1)*64);
            if (ch < 15){
                #pragma unroll
                for (int k=0; k<8; k++) cv[k] = nv[k];
            }
        }

        // normals: trilinear of normalized-normals grid, then renormalize+negate
        float nsx = 0.f, nsy = 0.f, nsz = 0.f;
        #pragma unroll
        for (int k=0; k<8; k++){
            nsx = fmaf(wc[k], __ldg(g_norm + off[k]),          nsx);
            nsy = fmaf(wc[k], __ldg(g_norm + NVOX + off[k]),   nsy);
            nsz = fmaf(wc[k], __ldg(g_norm + 2*NVOX + off[k]), nsz);
        }
        float nl = sqrtf(nsx*nsx + nsy*nsy + nsz*nsz);
        float ninv = -1.f / fmaxf(nl, 1e-12f);
        nsx *= ninv; nsy *= ninv; nsz *= ninv;
        float dt  = -(vx*nsx + vy*nsy + vz*nsz);
        float rx = fmaf(2.f*dt, nsx, vx);
        float ry = fmaf(2.f*dt, nsy, vy);
        float rz = fmaf(2.f*dt, nsz, vz);

        // feat 15..17: refdir
        accum_row(h, rx, sh + OFF_W0 + 15*64);
        accum_row(h, ry, sh + OFF_W0 + 16*64);
        accum_row(h, rz, sh + OFF_W0 + 17*64);

        // feat 18..35 sin, 36..53 cos (freq-major order: f*3+k)
        float rv0 = rx, rv1 = ry, rv2 = rz;
        for (int f=0; f<6; ++f){
            float fr = (float)(1 << f);
            #pragma unroll
            for (int k3=0; k3<3; k3++){
                float ang = (k3==0 ? rv0 : (k3==1 ? rv1 : rv2)) * fr;
                // own range reduction so fast-math sin stays accurate
                float kk = rintf(ang * 0.15915494309189535f);
                float r2 = fmaf(kk, -6.283185307179586f, ang);
                float sn, cs;
                sincosf(r2, &sn, &cs);
                int rowi = 18 + f*3 + k3;
                accum_row(h, sn, sh + OFF_W0 + rowi*64);
                accum_row(h, cs, sh + OFF_W0 + (rowi+18)*64);
            }
        }

        // relu -> stage
        #pragma unroll
        for (int k=0; k<32; k++){
            float lo, hi; f2unpack(h[k], lo, hi);
            hst[2*k]   = fmaxf(lo, 0.f);
            hst[2*k+1] = fmaxf(hi, 0.f);
        }
        // layer 1
        {
            const u64* bp = (const u64*)(sh + OFF_B1);
            #pragma unroll
            for (int k=0; k<32; k++) h[k] = bp[k];
        }
        for (int i=0; i<64; i++) accum_row(h, hst[i], sh + OFF_W1 + i*64);
        #pragma unroll
        for (int k=0; k<32; k++){
            float lo, hi; f2unpack(h[k], lo, hi);
            hst[2*k]   = fmaxf(lo, 0.f);
            hst[2*k+1] = fmaxf(hi, 0.f);
        }
        // layer 2
        {
            const u64* bp = (const u64*)(sh + OFF_B2);
            #pragma unroll
            for (int k=0; k<32; k++) h[k] = bp[k];
        }
        for (int i=0; i<64; i++) accum_row(h, hst[i], sh + OFF_W2 + i*64);
        #pragma unroll
        for (int k=0; k<32; k++){
            float lo, hi; f2unpack(h[k], lo, hi);
            hst[2*k]   = fmaxf(lo, 0.f);
            hst[2*k+1] = fmaxf(hi, 0.f);
        }
        // layer 3 (64 -> 3) + sigmoid
        float c0s = sh[OFF_B3+0], c1s = sh[OFF_B3+1], c2s = sh[OFF_B3+2];
        for (int i=0; i<64; i++){
            float v = hst[i];
            c0s = fmaf(v, sh[OFF_W3 + i*3 + 0], c0s);
            c1s = fmaf(v, sh[OFF_W3 + i*3 + 1], c1s);
            c2s = fmaf(v, sh[OFF_W3 + i*3 + 2], c2s);
        }
        float col0 = 1.f / (1.f + expf(-c0s));
        float col1 = 1.f / (1.f + expf(-c1s));
        float col2 = 1.f / (1.f + expf(-c2s));
        acc0 = fmaf(wgt, col0, acc0);
        acc1 = fmaf(wgt, col1, acc1);
        acc2 = fmaf(wgt, col2, acc2);
    }

    // deterministic block reduction
    #pragma unroll
    for (int o2=16; o2; o2>>=1){
        acc0 += __shfl_down_sync(0xffffffffu, acc0, o2);
        acc1 += __shfl_down_sync(0xffffffffu, acc1, o2);
        acc2 += __shfl_down_sync(0xffffffffu, acc2, o2);
    }
    int lane = tid & 31, wrp = tid >> 5;
    if (lane == 0){
        sh[OFF_RED + wrp*3 + 0] = acc0;
        sh[OFF_RED + wrp*3 + 1] = acc1;
        sh[OFF_RED + wrp*3 + 2] = acc2;
    }
    __syncthreads();
    if (tid == 0){
        float Tf = sh[OFF_RED + 15];
        float r0 = sh[OFF_RED+0] + sh[OFF_RED+3] + sh[OFF_RED+6] + sh[OFF_RED+9];
        float r1 = sh[OFF_RED+1] + sh[OFF_RED+4] + sh[OFF_RED+7] + sh[OFF_RED+10];
        float r2 = sh[OFF_RED+2] + sh[OFF_RED+5] + sh[OFF_RED+8] + sh[OFF_RED+11];
        out[rid*3+0] = r0 + Tf;   // BG = 1.0
        out[rid*3+1] = r1 + Tf;
        out[rid*3+2] = r2 + Tf;
    }
}

extern "C" void kernel_launch(void* const* d_in, const int* in_sizes, int n_in,
                              void* d_out, int out_size)
{
    (void)in_sizes; (void)n_in; (void)out_size;
    const float* ro    = (const float*)d_in[0];
    const float* rd    = (const float*)d_in[1];
    const float* vd    = (const float*)d_in[2];
    const float* grid  = (const float*)d_in[3];
    const float* sobel = (const float*)d_in[4];
    const float* w0 = (const float*)d_in[5];
    const float* b0 = (const float*)d_in[6];
    const float* w1 = (const float*)d_in[7];
    const float* b1 = (const float*)d_in[8];
    const float* w2 = (const float*)d_in[9];
    const float* b2 = (const float*)d_in[10];
    const float* w3 = (const float*)d_in[11];
    const float* b3 = (const float*)d_in[12];
    float* out = (float*)d_out;

    conv_kernel<<<dim3(4,16,32), dim3(32,8,1)>>>(grid, sobel);

    cudaFuncSetAttribute(march_kernel,
                         cudaFuncAttributeMaxDynamicSharedMemorySize, SMEM_BYTES);
    march_kernel<<<NRAYS, NTH, SMEM_BYTES>>>(ro, rd, vd, grid,
                                             w0, b0, w1, b1, w2, b2, w3, b3, out);
}

// round 2
// speedup vs baseline: 1.2365x; 1.2365x over previous
#include <cuda_runtime.h>
#include <math.h>

#define RESX   128
#define NVOX   (RESX*RESX*RESX)
#define NRAYS  1024
#define NS     891

#define ACT_SHIFT (-4.5951198501345898f)   // log(1/(1-0.01)-1)

// ---------------- global scratch (device globals: allowed) ----------------
__device__ float g_norm[3*NVOX];          // normalized sobel normals
__device__ float g_w[NRAYS*NS];           // per-sample weights (in-box range only)
__device__ float g_T[NRAYS];              // final transmittance
__device__ float g_tmin[NRAYS];
__device__ float g_invn[NRAYS];
__device__ int   g_sstart[NRAYS];
__device__ int   g_scnt[NRAYS];
__device__ int   g_base[NRAYS+1];         // exclusive prefix of scnt
__device__ int   g_total;
__device__ float g_c0[NRAYS*NS];
__device__ float g_c1[NRAYS*NS];
__device__ float g_c2[NRAYS*NS];

// ---------------------------------------------------------------------------
// Kernel 1: 5x5x5 conv of density with sobel kernel, zero pad 2, normalize.
// ---------------------------------------------------------------------------
__global__ void __launch_bounds__(256) conv_kernel(const float* __restrict__ dens,
                                                   const float* __restrict__ kern)
{
    __shared__ float sk[375];
    __shared__ float tile[8*12*36];

    int tc = threadIdx.x;          // 0..31 (c fastest)
    int tb = threadIdx.y;          // 0..7
    int tid = tb*32 + tc;
    int c0 = blockIdx.x*32;
    int b0 = blockIdx.y*8;
    int a0 = blockIdx.z*4;

    for (int i=tid; i<375; i+=256) sk[i] = kern[i];
    for (int i=tid; i<8*12*36; i+=256){
        int ic = i % 36; int r = i / 36; int ib = r % 12; int ia = r / 12;
        int ga = a0 - 2 + ia, gb = b0 - 2 + ib, gc = c0 - 2 + ic;
        float v = 0.f;
        if ((unsigned)ga < 128u && (unsigned)gb < 128u && (unsigned)gc < 128u)
            v = dens[(ga*128 + gb)*128 + gc];
        tile[i] = v;
    }
    __syncthreads();

    float s0[4] = {0,0,0,0}, s1[4] = {0,0,0,0}, s2[4] = {0,0,0,0};
    for (int db=0; db<5; db++){
        for (int dc=0; dc<5; dc++){
            float tv[8];
            #pragma unroll
            for (int ia=0; ia<8; ia++)
                tv[ia] = tile[(ia*12 + tb + db)*36 + tc + dc];
            #pragma unroll
            for (int da=0; da<5; da++){
                float k0 = sk[0*125 + da*25 + db*5 + dc];
                float k1 = sk[1*125 + da*25 + db*5 + dc];
                float k2 = sk[2*125 + da*25 + db*5 + dc];
                #pragma unroll
                for (int v=0; v<4; v++){
                    float x = tv[v+da];
                    s0[v] = fmaf(k0, x, s0[v]);
                    s1[v] = fmaf(k1, x, s1[v]);
                    s2[v] = fmaf(k2, x, s2[v]);
                }
            }
        }
    }
    #pragma unroll
    for (int v=0; v<4; v++){
        int idx = ((a0+v)*128 + (b0+tb))*128 + (c0+tc);
        float n0 = s0[v], n1 = s1[v], n2 = s2[v];
        float len = sqrtf(n0*n0 + n1*n1 + n2*n2);
        float inv = -1.f / fmaxf(len, 1e-12f);
        g_norm[idx]          = n0*inv;
        g_norm[NVOX + idx]   = n1*inv;
        g_norm[2*NVOX + idx] = n2*inv;
    }
}

// ---------------------------------------------------------------------------
// packed fp32x2 helpers
// ---------------------------------------------------------------------------
typedef unsigned long long u64;
__device__ __forceinline__ u64 f2pack(float lo, float hi){
    u64 r; asm("mov.b64 %0,{%1,%2};" : "=l"(r) : "f"(lo), "f"(hi)); return r;
}
__device__ __forceinline__ void f2unpack(u64 v, float& lo, float& hi){
    asm("mov.b64 {%0,%1},%2;" : "=f"(lo), "=f"(hi) : "l"(v));
}
__device__ __forceinline__ u64 ffma2(u64 a, u64 b, u64 c){
    u64 d; asm("fma.rn.f32x2 %0,%1,%2,%3;" : "=l"(d) : "l"(a), "l"(b), "l"(c)); return d;
}
// h[32] += v * row[0..63], weights fetched as 16B vectors (halved LDS count)
__device__ __forceinline__ void accum_row(u64* h, float v, const float* row){
    u64 vv = f2pack(v, v);
    const ulonglong2* wr = (const ulonglong2*)row;
    #pragma unroll
    for (int k=0; k<16; k++){
        ulonglong2 w2 = wr[k];
        h[2*k]   = ffma2(vv, w2.x, h[2*k]);
        h[2*k+1] = ffma2(vv, w2.y, h[2*k+1]);
    }
}

__device__ __forceinline__ void tri_setup(float px, float py, float pz,
                                          int* off, float* w)
{
    float ga = (px + 1.f)*0.5f*127.f;
    float gb = (py + 1.f)*0.5f*127.f;
    float gc = (pz + 1.f)*0.5f*127.f;
    float fa0 = floorf(ga), fb0 = floorf(gb), fc0 = floorf(gc);
    float fa = ga - fa0, fb = gb - fb0, fc = gc - fc0;
    int a0 = min(max((int)fa0, 0), 127);
    int b0 = min(max((int)fb0, 0), 127);
    int c0 = min(max((int)fc0, 0), 127);
    int a1 = min(a0+1, 127), b1 = min(b0+1, 127), c1 = min(c0+1, 127);
    int A0 = a0*16384, A1 = a1*16384, B0 = b0*128, B1 = b1*128;
    off[0]=A0+B0+c0; off[1]=A0+B0+c1; off[2]=A0+B1+c0; off[3]=A0+B1+c1;
    off[4]=A1+B0+c0; off[5]=A1+B0+c1; off[6]=A1+B1+c0; off[7]=A1+B1+c1;
    float wa0 = 1.f-fa, wb0 = 1.f-fb, wc0 = 1.f-fc;
    w[0]=wa0*wb0*wc0; w[1]=wa0*wb0*fc; w[2]=wa0*fb*wc0; w[3]=wa0*fb*fc;
    w[4]=fa*wb0*wc0;  w[5]=fa*wb0*fc;  w[6]=fa*fb*wc0;  w[7]=fa*fb*fc;
}

// ---------------------------------------------------------------------------
// Kernel 2: per-ray prep. alpha per sample, transmittance scan, in-box
// interval + weights to global.
// ---------------------------------------------------------------------------
__global__ void __launch_bounds__(128) prep_kernel(
    const float* __restrict__ ro, const float* __restrict__ rdv,
    const float* __restrict__ grid)
{
    __shared__ float aw[NS];
    __shared__ int s_min, s_max;
    int tid = threadIdx.x;
    int rid = blockIdx.x;
    if (tid == 0){ s_min = 0x7fffffff; s_max = -1; }
    __syncthreads();

    float ox = ro[rid*3+0], oy = ro[rid*3+1], oz = ro[rid*3+2];
    float dx = rdv[rid*3+0], dy = rdv[rid*3+1], dz = rdv[rid*3+2];

    float vecx = (dx == 0.f) ? 1e-6f : dx;
    float vecy = (dy == 0.f) ? 1e-6f : dy;
    float vecz = (dz == 0.f) ? 1e-6f : dz;
    float rax = ( 1.f - ox)/vecx, rbx = (-1.f - ox)/vecx;
    float ray_ = ( 1.f - oy)/vecy, rby = (-1.f - oy)/vecy;
    float raz = ( 1.f - oz)/vecz, rbz = (-1.f - oz)/vecz;
    float tmin = fmaxf(fmaxf(fminf(rax,rbx), fminf(ray_,rby)), fminf(raz,rbz));
    tmin = fminf(fmaxf(tmin, 0.2f), 3.0f);
    float tmax = fminf(fminf(fmaxf(rax,rbx), fmaxf(ray_,rby)), fmaxf(raz,rbz));
    tmax = fminf(fmaxf(tmax, 0.2f), 3.0f);
    bool maskray = (tmax <= tmin);
    float invn = 1.f / sqrtf(dx*dx + dy*dy + dz*dz);

    int lmin = 0x7fffffff, lmax = -1;
    for (int s=tid; s<NS; s+=128){
        float t  = tmin + (0.0078125f * (float)s) * invn;
        float px = fmaf(dx, t, ox), py = fmaf(dy, t, oy), pz = fmaf(dz, t, oz);
        bool in = (!maskray) &&
                  !(px < -1.f || px > 1.f || py < -1.f || py > 1.f || pz < -1.f || pz > 1.f);
        float a = 0.f;
        if (in){
            int off[8]; float wc[8];
            tri_setup(px, py, pz, off, wc);
            float l0 = 0.f;
            #pragma unroll
            for (int k=0; k<8; k++) l0 = fmaf(wc[k], __ldg(grid + off[k]), l0);
            float xs = l0 + ACT_SHIFT;
            float sp = fmaxf(xs, 0.f) + log1pf(expf(-fabsf(xs)));
            a = 1.f - expf(-sp*0.5f);
            lmin = min(lmin, s); lmax = max(lmax, s);
        }
        aw[s] = a;
    }
    if (lmax >= 0){ atomicMin(&s_min, lmin); atomicMax(&s_max, lmax); }
    __syncthreads();

    if (tid == 0){
        float T = 1.f;
        for (int s=0; s<NS; s++){
            float a = aw[s];
            aw[s] = a * T;
            T *= fmaxf(1.f - a, 1e-10f);
        }
        g_T[rid]    = T;
        g_tmin[rid] = tmin;
        g_invn[rid] = invn;
        int cnt = (s_max >= s_min) ? (s_max - s_min + 1) : 0;
        g_sstart[rid] = (cnt > 0) ? s_min : 0;
        g_scnt[rid]   = cnt;
    }
    __syncthreads();

    int smn = s_min, smx = s_max;
    if (smx >= smn){
        for (int s=smn+tid; s<=smx; s+=128)
            g_w[rid*NS + s] = aw[s];
    }
}

// ---------------------------------------------------------------------------
// Kernel 3: exclusive prefix sum over 1024 ray counts.
// ---------------------------------------------------------------------------
__global__ void __launch_bounds__(1024) scan_kernel()
{
    __shared__ int tmp[NRAYS];
    int t = threadIdx.x;
    tmp[t] = g_scnt[t];
    __syncthreads();
    for (int o=1; o<NRAYS; o<<=1){
        int a = (t >= o) ? tmp[t-o] : 0;
        __syncthreads();
        tmp[t] += a;
        __syncthreads();
    }
    g_base[t+1] = tmp[t];
    if (t == 0) g_base[0] = 0;
    if (t == NRAYS-1) g_total = tmp[t];
}

// ---------------------------------------------------------------------------
// Kernel 4: balanced MLP over dense entry list.
// ---------------------------------------------------------------------------
#define OFF_W0   0
#define OFF_B0   3456
#define OFF_W1   3520
#define OFF_B1   7616
#define OFF_W2   7680
#define OFF_B2   11776
#define OFF_W3   11840
#define OFF_B3   12032
#define OFF_BASE 12036
#define OFF_HST  13064
#define SH_FLOATS (13064 + 128*65)
#define SMEM_MLP (SH_FLOATS*4)
#define MLP_BLOCKS 296
#define MLP_NTH 128

__global__ void __launch_bounds__(MLP_NTH) mlp_kernel(
    const float* __restrict__ ro,  const float* __restrict__ rdv,
    const float* __restrict__ vdv, const float* __restrict__ grid,
    const float* __restrict__ w0,  const float* __restrict__ b0,
    const float* __restrict__ w1,  const float* __restrict__ b1,
    const float* __restrict__ w2,  const float* __restrict__ b2,
    const float* __restrict__ w3,  const float* __restrict__ b3)
{
    extern __shared__ float sh[];
    int tid = threadIdx.x;
    int* sbase = (int*)(sh + OFF_BASE);

    for (int i=tid; i<3456; i+=MLP_NTH) sh[OFF_W0+i] = w0[i];
    for (int i=tid; i<64;   i+=MLP_NTH) sh[OFF_B0+i] = b0[i];
    for (int i=tid; i<4096; i+=MLP_NTH) sh[OFF_W1+i] = w1[i];
    for (int i=tid; i<64;   i+=MLP_NTH) sh[OFF_B1+i] = b1[i];
    for (int i=tid; i<4096; i+=MLP_NTH) sh[OFF_W2+i] = w2[i];
    for (int i=tid; i<64;   i+=MLP_NTH) sh[OFF_B2+i] = b2[i];
    for (int i=tid; i<192;  i+=MLP_NTH) sh[OFF_W3+i] = w3[i];
    if (tid < 3) sh[OFF_B3+tid] = b3[tid];
    for (int i=tid; i<NRAYS+1; i+=MLP_NTH) sbase[i] = g_base[i];
    __syncthreads();

    int total = g_total;
    float* hst = sh + OFF_HST + tid*65;

    for (int e = blockIdx.x*MLP_NTH + tid; e < total; e += MLP_BLOCKS*MLP_NTH){
        // binary search: largest ray with sbase[ray] <= e
        int lo = 0, hi = NRAYS;
        while (hi - lo > 1){
            int mid = (lo + hi) >> 1;
            if (sbase[mid] <= e) lo = mid; else hi = mid;
        }
        int ray = lo;
        int s = g_sstart[ray] + (e - sbase[ray]);

        float ox = __ldg(ro+ray*3+0), oy = __ldg(ro+ray*3+1), oz = __ldg(ro+ray*3+2);
        float dx = __ldg(rdv+ray*3+0), dy = __ldg(rdv+ray*3+1), dz = __ldg(rdv+ray*3+2);
        float vx = __ldg(vdv+ray*3+0), vy = __ldg(vdv+ray*3+1), vz = __ldg(vdv+ray*3+2);
        float tmin = __ldg(&g_tmin[ray]);
        float invn = __ldg(&g_invn[ray]);
        float wgt  = __ldg(&g_w[ray*NS + s]);

        float t  = tmin + (0.0078125f * (float)s) * invn;
        float px = fmaf(dx, t, ox), py = fmaf(dy, t, oy), pz = fmaf(dz, t, oz);

        int off[8]; float wc[8];
        tri_setup(px, py, pz, off, wc);

        // prefetch normal-grid gathers (24 outstanding loads)
        float nvx[8], nvy[8], nvz[8];
        #pragma unroll
        for (int k=0; k<8; k++){
            nvx[k] = __ldg(g_norm + off[k]);
            nvy[k] = __ldg(g_norm + NVOX + off[k]);
            nvz[k] = __ldg(g_norm + 2*NVOX + off[k]);
        }

        // layer 0 accumulators
        u64 h[32];
        {
            const ulonglong2* bp = (const ulonglong2*)(sh + OFF_B0);
            #pragma unroll
            for (int k=0; k<16; k++){
                ulonglong2 b2v = bp[k];
                h[2*k] = b2v.x; h[2*k+1] = b2v.y;
            }
        }

        // rgb latent channels 1..15, 1-ahead prefetch
        float cv[8];
        #pragma unroll
        for (int k=0; k<8; k++) cv[k] = __ldg(grid + NVOX + off[k]);
        for (int ch=1; ch<=15; ++ch){
            float nv[8];
            if (ch < 15){
                const float* gp = grid + (ch+1)*NVOX;
                #pragma unroll
                for (int k=0; k<8; k++) nv[k] = __ldg(gp + off[k]);
            }
            float v = 0.f;
            #pragma unroll
            for (int k=0; k<8; k++) v = fmaf(wc[k], cv[k], v);
            accum_row(h, v, sh + OFF_W0 + (ch-1)*64);
            if (ch < 15){
                #pragma unroll
                for (int k=0; k<8; k++) cv[k] = nv[k];
            }
        }

        // normals trilinear + renormalize + reflect
        float nsx = 0.f, nsy = 0.f, nsz = 0.f;
        #pragma unroll
        for (int k=0; k<8; k++){
            nsx = fmaf(wc[k], nvx[k], nsx);
            nsy = fmaf(wc[k], nvy[k], nsy);
            nsz = fmaf(wc[k], nvz[k], nsz);
        }
        float nl = sqrtf(nsx*nsx + nsy*nsy + nsz*nsz);
        float ninv = -1.f / fmaxf(nl, 1e-12f);
        nsx *= ninv; nsy *= ninv; nsz *= ninv;
        float dt  = -(vx*nsx + vy*nsy + vz*nsz);
        float rx = fmaf(2.f*dt, nsx, vx);
        float ry = fmaf(2.f*dt, nsy, vy);
        float rz = fmaf(2.f*dt, nsz, vz);

        accum_row(h, rx, sh + OFF_W0 + 15*64);
        accum_row(h, ry, sh + OFF_W0 + 16*64);
        accum_row(h, rz, sh + OFF_W0 + 17*64);

        for (int f=0; f<6; ++f){
            float fr = (float)(1 << f);
            #pragma unroll
            for (int k3=0; k3<3; k3++){
                float ang = (k3==0 ? rx : (k3==1 ? ry : rz)) * fr;
                float kk = rintf(ang * 0.15915494309189535f);
                float r2 = fmaf(kk, -6.283185307179586f, ang);
                float sn, cs;
                sincosf(r2, &sn, &cs);
                int rowi = 18 + f*3 + k3;
                accum_row(h, sn, sh + OFF_W0 + rowi*64);
                accum_row(h, cs, sh + OFF_W0 + (rowi+18)*64);
            }
        }

        // relu -> stage
        #pragma unroll
        for (int k=0; k<32; k++){
            float flo, fhi; f2unpack(h[k], flo, fhi);
            hst[2*k]   = fmaxf(flo, 0.f);
            hst[2*k+1] = fmaxf(fhi, 0.f);
        }
        // layer 1
        {
            const ulonglong2* bp = (const ulonglong2*)(sh + OFF_B1);
            #pragma unroll
            for (int k=0; k<16; k++){
                ulonglong2 b2v = bp[k];
                h[2*k] = b2v.x; h[2*k+1] = b2v.y;
            }
        }
        for (int i=0; i<64; i++) accum_row(h, hst[i], sh + OFF_W1 + i*64);
        #pragma unroll
        for (int k=0; k<32; k++){
            float flo, fhi; f2unpack(h[k], flo, fhi);
            hst[2*k]   = fmaxf(flo, 0.f);
            hst[2*k+1] = fmaxf(fhi, 0.f);
        }
        // layer 2
        {
            const ulonglong2* bp = (const ulonglong2*)(sh + OFF_B2);
            #pragma unroll
            for (int k=0; k<16; k++){
                ulonglong2 b2v = bp[k];
                h[2*k] = b2v.x; h[2*k+1] = b2v.y;
            }
        }
        for (int i=0; i<64; i++) accum_row(h, hst[i], sh + OFF_W2 + i*64);
        #pragma unroll
        for (int k=0; k<32; k++){
            float flo, fhi; f2unpack(h[k], flo, fhi);
            hst[2*k]   = fmaxf(flo, 0.f);
            hst[2*k+1] = fmaxf(fhi, 0.f);
        }
        // layer 3 + sigmoid
        float c0s = sh[OFF_B3+0], c1s = sh[OFF_B3+1], c2s = sh[OFF_B3+2];
        for (int i=0; i<64; i++){
            float v = hst[i];
            c0s = fmaf(v, sh[OFF_W3 + i*3 + 0], c0s);
            c1s = fmaf(v, sh[OFF_W3 + i*3 + 1], c1s);
            c2s = fmaf(v, sh[OFF_W3 + i*3 + 2], c2s);
        }
        float col0 = 1.f / (1.f + expf(-c0s));
        float col1 = 1.f / (1.f + expf(-c1s));
        float col2 = 1.f / (1.f + expf(-c2s));
        g_c0[e] = wgt * col0;
        g_c1[e] = wgt * col1;
        g_c2[e] = wgt * col2;
    }
}

// ---------------------------------------------------------------------------
// Kernel 5: per-ray deterministic reduction + background.
// ---------------------------------------------------------------------------
__global__ void __launch_bounds__(32) reduce_kernel(float* __restrict__ out)
{
    int ray = blockIdx.x;
    int lane = threadIdx.x;
    int base = g_base[ray];
    int cnt  = g_base[ray+1] - base;
    float a0 = 0.f, a1 = 0.f, a2 = 0.f;
    for (int i=lane; i<cnt; i+=32){
        a0 += g_c0[base+i];
        a1 += g_c1[base+i];
        a2 += g_c2[base+i];
    }
    #pragma unroll
    for (int o=16; o; o>>=1){
        a0 += __shfl_down_sync(0xffffffffu, a0, o);
        a1 += __shfl_down_sync(0xffffffffu, a1, o);
        a2 += __shfl_down_sync(0xffffffffu, a2, o);
    }
    if (lane == 0){
        float Tf = g_T[ray];        // BG = 1.0
        out[ray*3+0] = a0 + Tf;
        out[ray*3+1] = a1 + Tf;
        out[ray*3+2] = a2 + Tf;
    }
}

extern "C" void kernel_launch(void* const* d_in, const int* in_sizes, int n_in,
                              void* d_out, int out_size)
{
    (void)in_sizes; (void)n_in; (void)out_size;
    const float* ro    = (const float*)d_in[0];
    const float* rd    = (const float*)d_in[1];
    const float* vd    = (const float*)d_in[2];
    const float* grid  = (const float*)d_in[3];
    const float* sobel = (const float*)d_in[4];
    const float* w0 = (const float*)d_in[5];
    const float* b0 = (const float*)d_in[6];
    const float* w1 = (const float*)d_in[7];
    const float* b1 = (const float*)d_in[8];
    const float* w2 = (const float*)d_in[9];
    const float* b2 = (const float*)d_in[10];
    const float* w3 = (const float*)d_in[11];
    const float* b3 = (const float*)d_in[12];
    float* out = (float*)d_out;

    conv_kernel<<<dim3(4,16,32), dim3(32,8,1)>>>(grid, sobel);
    prep_kernel<<<NRAYS, 128>>>(ro, rd, grid);
    scan_kernel<<<1, 1024>>>();

    static int smem_set = 0;
    if (!smem_set){
        cudaFuncSetAttribute(mlp_kernel,
                             cudaFuncAttributeMaxDynamicSharedMemorySize, SMEM_MLP);
        smem_set = 1;
    }
    mlp_kernel<<<MLP_BLOCKS, MLP_NTH, SMEM_MLP>>>(ro, rd, vd, grid,
                                                  w0, b0, w1, b1, w2, b2, w3, b3);
    reduce_kernel<<<NRAYS, 32>>>(out);
}